// round 6
// baseline (speedup 1.0000x reference)
#include <cuda_runtime.h>

#define B_   2048
#define T_   128
#define S_   256
#define H_   64
#define E_   32
#define V_   29
#define G4   256   // 4*H
#define ES   68    // enc SMEM row stride (floats); halves at +0 and +34

typedef unsigned long long ull;

struct __align__(16) Smem {
    float enc[S_ * ES];        // 69632 B
    float gate_emb[V_ * G4];   // 29696 B : W_ih[:, :32]@emb[v] + b_ih + b_hh
    float fcW[V_ * 128 + 32];  // 14976 B
    float embS[V_ * E_];       //  3712 B (prologue only)
    float part[16 * 64];       //  4096 B
    float scores[S_];
    float gpart[2 * G4];       // [0:256)=W_hh@h, [256:512)=W_ih_ctx@ctx
    float bias[G4];            // prologue only
    float comb[128];           // [0:64)=h [64:128)=ctx (fc input)
    float hdup[72];            // h halves at 0 / 40 (bank offset)
    float cdup[72];            // ctx halves at 0 / 40
    float fcb[32];
    float redsum[16];
    int   ytok[T_];
};

__device__ __forceinline__ ull pack2(float lo, float hi) {
    ull r; asm("mov.b64 %0, {%1, %2};" : "=l"(r) : "f"(lo), "f"(hi)); return r;
}
__device__ __forceinline__ ull fma2(ull a, ull b, ull c) {
    ull d; asm("fma.rn.f32x2 %0, %1, %2, %3;" : "=l"(d) : "l"(a), "l"(b), "l"(c));
    return d;
}
__device__ __forceinline__ float2 unpack2(ull v) {
    float lo, hi; asm("mov.b64 {%0, %1}, %2;" : "=f"(lo), "=f"(hi) : "l"(v));
    return make_float2(lo, hi);
}
__device__ __forceinline__ float sigmoid_(float z) {
    return 1.0f / (1.0f + __expf(-z));
}
__device__ __forceinline__ float tanh_(float x) {
    return 1.0f - 2.0f / (__expf(2.0f * x) + 1.0f);
}

extern "C" __global__ void __launch_bounds__(512, 1)
decoder_persist_kernel(const int* __restrict__ y,
                       const float* __restrict__ h0,
                       const float* __restrict__ c0,
                       const float* __restrict__ enc_g,
                       const float* __restrict__ embt,
                       const float* __restrict__ Wih,
                       const float* __restrict__ Whh,
                       const float* __restrict__ bih,
                       const float* __restrict__ bhh,
                       const float* __restrict__ fcWg,
                       const float* __restrict__ fcbg,
                       float* __restrict__ out)
{
    extern __shared__ __align__(16) char smem_raw[];
    Smem& sm = *reinterpret_cast<Smem*>(smem_raw);
    const int tid  = threadIdx.x;
    const int b    = blockIdx.x;
    const int lane = tid & 31;
    const int wrp  = tid >> 5;
    const int r    = tid >> 1;   // P1 score row / prologue gate row
    const int half = tid & 1;
    const int prow = tid & 255;  // P4 gate row

    // ---- stage enc (mid-row pad), weights, constants ----
    {
        const float2* eb = reinterpret_cast<const float2*>(enc_g + (size_t)b * (S_ * H_));
        for (int i2 = tid; i2 < (S_ * H_) / 2; i2 += 512) {
            float2 v = eb[i2];
            int s  = i2 >> 5;
            int h2 = (i2 & 31) << 1;
            int dst = s * ES + h2 + ((h2 >= 32) ? 2 : 0);
            *reinterpret_cast<float2*>(&sm.enc[dst]) = v;
        }
    }
    for (int i = tid; i < V_ * 128; i += 512) sm.fcW[i] = fcWg[i];
    for (int i = tid; i < V_ * E_;  i += 512) sm.embS[i] = embt[i];
    if (tid < G4) sm.bias[tid] = bih[tid] + bhh[tid];
    if (tid < V_) sm.fcb[tid]  = fcbg[tid];
    if (tid < T_) sm.ytok[tid] = y[b * T_ + tid];
    float creg = 0.0f;
    if (tid < H_) {
        float hv = h0[b * H_ + tid];
        sm.comb[tid] = hv;
        sm.hdup[tid + ((tid >> 5) << 3)] = hv;   // halves at 0 / 40
        creg = c0[b * H_ + tid];
    }
    __syncthreads();

    // ---- prologue: gate_emb[v][r] = W_ih[r, :32].emb[v] + bias[r] ----
    {
        float4 we[4];
        const float4* wg = reinterpret_cast<const float4*>(Wih + r * 96 + 16 * half);
        #pragma unroll
        for (int k = 0; k < 4; k++) we[k] = wg[k];
        float brow = sm.bias[r];
        for (int v = 0; v < V_; v++) {
            const float4* em = reinterpret_cast<const float4*>(sm.embS + v * E_ + 16 * half);
            float a = 0.f;
            #pragma unroll
            for (int k = 0; k < 4; k++) {
                float4 e = em[k];
                a += we[k].x*e.x + we[k].y*e.y + we[k].z*e.z + we[k].w*e.w;
            }
            a += __shfl_xor_sync(0xffffffffu, a, 1);
            if (half == 0) sm.gate_emb[v * G4 + r] = a + brow;
        }
    }

    // ---- persistent weight row (64 floats = 32 ull = 64 regs) ----
    // tid<256: W_hh row prow; tid>=256: W_ih ctx-part row prow
    ull wl2[16], wu2[16];
    {
        const float4* wp = reinterpret_cast<const float4*>(
            (tid < 256) ? (Whh + prow * 64) : (Wih + prow * 96 + 32));
        #pragma unroll
        for (int k = 0; k < 8; k++) {
            float4 v = wp[k];
            wl2[2*k] = pack2(v.x, v.y); wl2[2*k+1] = pack2(v.z, v.w);
        }
        #pragma unroll
        for (int k = 0; k < 8; k++) {
            float4 v = wp[8 + k];
            wu2[2*k] = pack2(v.x, v.y); wu2[2*k+1] = pack2(v.z, v.w);
        }
    }
    __syncthreads();

    float* outp = out + (size_t)b * T_ * V_;

    for (int t = 0; t < T_; t++) {
        // ---- P1: e_s = exp(enc[s,:].h)  (2 threads per s, f32x2) — as R3 ----
        {
            const ull* ep = reinterpret_cast<const ull*>(sm.enc + r * ES + half * 34);
            const ull* hp = reinterpret_cast<const ull*>(sm.hdup + half * 40);
            ull a0 = 0ull, a1 = 0ull;
            #pragma unroll
            for (int k = 0; k < 16; k += 2) {
                a0 = fma2(ep[k],     hp[k],     a0);
                a1 = fma2(ep[k + 1], hp[k + 1], a1);
            }
            float2 fa = unpack2(a0), fb = unpack2(a1);
            float sc = (fa.x + fa.y) + (fb.x + fb.y);
            sc += __shfl_xor_sync(0xffffffffu, sc, 1);
            float e = __expf(sc);            // |sc| bounded: no overflow
            if (half == 0) sm.scores[r] = e;
            float su = e;
            #pragma unroll
            for (int o = 16; o > 1; o >>= 1)
                su += __shfl_xor_sync(0xffffffffu, su, o);
            // lane 0 = sum over even lanes = warp's 16 distinct scores, once each
            if (lane == 0) sm.redsum[wrp] = su;
        }
        __syncthreads();  // bar1: scores, redsum

        // ---- P3: context partials (warp q: 16 s-rows, float2 lanes) — as R3 ----
        {
            const int sbase = wrp * 16;
            const float*  ebase = sm.enc + sbase * ES + 2 * lane + ((lane >> 4) & 1) * 2;
            const float4* sp = reinterpret_cast<const float4*>(sm.scores + sbase);
            float ax = 0.f, ay = 0.f;
            #pragma unroll
            for (int c = 0; c < 4; c++) {
                float4 sv = sp[c];
                float2 e0 = *reinterpret_cast<const float2*>(ebase + (4*c + 0) * ES);
                float2 e1 = *reinterpret_cast<const float2*>(ebase + (4*c + 1) * ES);
                float2 e2 = *reinterpret_cast<const float2*>(ebase + (4*c + 2) * ES);
                float2 e3 = *reinterpret_cast<const float2*>(ebase + (4*c + 3) * ES);
                ax += sv.x * e0.x; ay += sv.x * e0.y;
                ax += sv.y * e1.x; ay += sv.y * e1.y;
                ax += sv.z * e2.x; ay += sv.z * e2.y;
                ax += sv.w * e3.x; ay += sv.w * e3.y;
            }
            *reinterpret_cast<float2*>(&sm.part[wrp * 64 + 2 * lane]) = make_float2(ax, ay);
        }
        __syncthreads();  // bar2: part

        // ---- ctx reduce + normalize -> comb[64:), cdup ----
        if (tid < H_) {
            float ssum = 0.f;
            #pragma unroll
            for (int k = 0; k < 16; k++) ssum += sm.redsum[k];
            float inv = 1.0f / ssum;
            float ctx = 0.f;
            #pragma unroll
            for (int q = 0; q < 16; q++) ctx += sm.part[q * 64 + tid];
            ctx *= inv;
            sm.comb[H_ + tid] = ctx;
            sm.cdup[tid + ((tid >> 5) << 3)] = ctx;   // halves at 0 / 40
        }
        __syncthreads();  // bar3: ctx

        // ---- P4: partial gates, full-row dot per thread.
        //      tid<256: gpart[row]     = W_hh[row,:]   . h
        //      tid>=256: gpart[256+row] = W_ih[row,32:] . ctx
        //      All lanes read the SAME vector -> pure broadcasts. ----
        {
            const float* vb = (tid < 256) ? sm.hdup : sm.cdup;
            const float4* v0 = reinterpret_cast<const float4*>(vb);        // [0:32)
            const float4* v1 = reinterpret_cast<const float4*>(vb + 40);   // [32:64)
            ull a0 = 0ull, a1 = 0ull;
            #pragma unroll
            for (int k = 0; k < 8; k++) {
                float4 xv = v0[k];
                a0 = fma2(wl2[2*k],   pack2(xv.x, xv.y), a0);
                a1 = fma2(wl2[2*k+1], pack2(xv.z, xv.w), a1);
            }
            #pragma unroll
            for (int k = 0; k < 8; k++) {
                float4 xv = v1[k];
                a0 = fma2(wu2[2*k],   pack2(xv.x, xv.y), a0);
                a1 = fma2(wu2[2*k+1], pack2(xv.z, xv.w), a1);
            }
            float2 fa = unpack2(a0), fb = unpack2(a1);
            sm.gpart[(tid & 256) + prow] = (fa.x + fa.y) + (fb.x + fb.y);
        }
        __syncthreads();  // bar4: gpart

        // ---- P5: combine + LSTM cell (torch order i,f,g,o) ----
        if (tid < H_) {
            int tok = sm.ytok[t];
            const float* ge = sm.gate_emb + tok * G4;
            float g0 = sm.gpart[tid]       + sm.gpart[256 + tid] + ge[tid];
            float g1 = sm.gpart[64 + tid]  + sm.gpart[320 + tid] + ge[64 + tid];
            float g2 = sm.gpart[128 + tid] + sm.gpart[384 + tid] + ge[128 + tid];
            float g3 = sm.gpart[192 + tid] + sm.gpart[448 + tid] + ge[192 + tid];
            creg = sigmoid_(g1) * creg + sigmoid_(g0) * tanh_(g2);
            float hnew = sigmoid_(g3) * tanh_(creg);
            sm.comb[tid] = hnew;
            sm.hdup[tid + ((tid >> 5) << 3)] = hnew;
        }
        __syncthreads();  // bar5: h

        // ---- P6: logits (16 threads per vocab row) ----
        {
            int v = tid >> 4, p = tid & 15;
            float acc = 0.0f;
            if (v < V_) {
                const float4* fw = reinterpret_cast<const float4*>(sm.fcW + v * 128 + p * 8);
                const float4* cb = reinterpret_cast<const float4*>(sm.comb + p * 8);
                float4 w0 = fw[0], w1 = fw[1];
                float4 c0v = cb[0], c1v = cb[1];
                acc = w0.x*c0v.x + w0.y*c0v.y + w0.z*c0v.z + w0.w*c0v.w
                    + w1.x*c1v.x + w1.y*c1v.y + w1.z*c1v.z + w1.w*c1v.w;
            }
            #pragma unroll
            for (int o = 8; o; o >>= 1)
                acc += __shfl_xor_sync(0xffffffffu, acc, o);
            if (p == 0 && v < V_)
                outp[t * V_ + v] = acc + sm.fcb[v];
        }
        // no trailing barrier: any later write to comb/hdup happens only after
        // bar2/bar4 of step t+1, which transitively require all warps past P6.
    }
}

extern "C" void kernel_launch(void* const* d_in, const int* in_sizes, int n_in,
                              void* d_out, int out_size) {
    const int*   y    = (const int*)d_in[0];
    const float* h0   = (const float*)d_in[1];
    const float* c0   = (const float*)d_in[2];
    const float* enc  = (const float*)d_in[3];
    const float* emb  = (const float*)d_in[4];
    const float* Wih  = (const float*)d_in[5];
    const float* Whh  = (const float*)d_in[6];
    const float* bih  = (const float*)d_in[7];
    const float* bhh  = (const float*)d_in[8];
    const float* fcW  = (const float*)d_in[9];
    const float* fcb  = (const float*)d_in[10];
    float* out = (float*)d_out;

    size_t smem = sizeof(Smem);
    cudaFuncSetAttribute(decoder_persist_kernel,
                         cudaFuncAttributeMaxDynamicSharedMemorySize, (int)smem);
    decoder_persist_kernel<<<B_, 512, smem>>>(y, h0, c0, enc, emb,
                                              Wih, Whh, bih, bhh, fcW, fcb, out);
}

// round 9
// speedup vs baseline: 1.1673x; 1.1673x over previous
#include <cuda_runtime.h>

#define B_   2048
#define T_   128
#define S_   256
#define H_   64
#define E_   32
#define V_   29
#define G4   256   // 4*H
#define ES   68    // enc SMEM row stride; halves at +0 and +34
#define NT   768   // 3 threads per gate row

typedef unsigned long long ull;

struct __align__(16) Smem {
    float enc[S_ * ES];        // 69632 B
    float gate_emb[V_ * G4];   // 29696 B : W_ih[:, :32]@emb[v] + b_ih + b_hh
    float fcW[V_ * 128 + 32];
    float embS[V_ * E_];       // prologue only
    float part[16 * 64];
    float scores[S_];
    float gpart[3 * G4];       // three K-slice partials per gate row
    float bias[G4];            // prologue only
    float comb[128];           // [0:64)=h [64:128)=ctx  (fc input)
    float hdup[72];            // h halves at 0 / 40 (bank offset) for P1
    float vec4[152];           // P4 vector: 48-float chunks at +0 / +52 / +104
                               //  ctx[0:48)->0..47, ctx[48:64)->52..67,
                               //  h[0:32)->68..99, h[32:64)->104..135,
                               //  pads 48..51 / 100..103 / 136..151 = 0
    float fcb[32];
    float redsum[16];
    int   ytok[T_];
};

__device__ __forceinline__ ull pack2(float lo, float hi) {
    ull r; asm("mov.b64 %0, {%1, %2};" : "=l"(r) : "f"(lo), "f"(hi)); return r;
}
__device__ __forceinline__ ull fma2(ull a, ull b, ull c) {
    ull d; asm("fma.rn.f32x2 %0, %1, %2, %3;" : "=l"(d) : "l"(a), "l"(b), "l"(c));
    return d;
}
__device__ __forceinline__ float2 unpack2(ull v) {
    float lo, hi; asm("mov.b64 {%0, %1}, %2;" : "=f"(lo), "=f"(hi) : "l"(v));
    return make_float2(lo, hi);
}
__device__ __forceinline__ float sigmoid_(float z) {
    return 1.0f / (1.0f + __expf(-z));
}
__device__ __forceinline__ float tanh_(float x) {
    return 1.0f - 2.0f / (__expf(2.0f * x) + 1.0f);
}

extern "C" __global__ void __launch_bounds__(NT, 1)
decoder_persist_kernel(const int* __restrict__ y,
                       const float* __restrict__ h0,
                       const float* __restrict__ c0,
                       const float* __restrict__ enc_g,
                       const float* __restrict__ embt,
                       const float* __restrict__ Wih,
                       const float* __restrict__ Whh,
                       const float* __restrict__ bih,
                       const float* __restrict__ bhh,
                       const float* __restrict__ fcWg,
                       const float* __restrict__ fcbg,
                       float* __restrict__ out)
{
    extern __shared__ __align__(16) char smem_raw[];
    Smem& sm = *reinterpret_cast<Smem*>(smem_raw);
    const int tid  = threadIdx.x;
    const int b    = blockIdx.x;
    const int lane = tid & 31;
    const int wrp  = tid >> 5;
    const int r    = tid >> 1;   // P1 score row (tid<512)
    const int half = tid & 1;
    const int r4   = tid / 3;    // P4 gate row (0..255)
    const int t3   = tid % 3;    // P4 K-slice (0..2)

    // ---- stage enc (mid-row pad), constants ----
    {
        const float2* eb = reinterpret_cast<const float2*>(enc_g + (size_t)b * (S_ * H_));
        for (int i2 = tid; i2 < (S_ * H_) / 2; i2 += NT) {
            float2 v = eb[i2];
            int s  = i2 >> 5;
            int h2 = (i2 & 31) << 1;
            int dst = s * ES + h2 + ((h2 >= 32) ? 2 : 0);
            *reinterpret_cast<float2*>(&sm.enc[dst]) = v;
        }
    }
    for (int i = tid; i < V_ * 128; i += NT) sm.fcW[i] = fcWg[i];
    for (int i = tid; i < V_ * E_;  i += NT) sm.embS[i] = embt[i];
    if (tid < G4) sm.bias[tid] = bih[tid] + bhh[tid];
    if (tid < V_) sm.fcb[tid]  = fcbg[tid];
    if (tid < T_) sm.ytok[tid] = y[b * T_ + tid];
    // zero ONLY the loop-invariant pad slots (no overlap with h0/ctx writers)
    if (tid < 16) sm.vec4[136 + tid] = 0.0f;
    if (tid < 4) { sm.vec4[48 + tid] = 0.0f; sm.vec4[100 + tid] = 0.0f; }
    float creg = 0.0f;
    if (tid < H_) {
        float hv = h0[b * H_ + tid];
        sm.comb[tid] = hv;
        sm.hdup[tid + ((tid >> 5) << 3)] = hv;               // halves at 0 / 40
        sm.vec4[(tid < 32) ? (68 + tid) : (72 + tid)] = hv;  // h chunks
        creg = c0[b * H_ + tid];
    }
    __syncthreads();

    // ---- prologue: gate_emb[v][r] = W_ih[r, :32].emb[v] + bias[r] ----
    if (tid < 512) {
        float4 we[4];
        const float4* wg = reinterpret_cast<const float4*>(Wih + r * 96 + 16 * half);
        #pragma unroll
        for (int k = 0; k < 4; k++) we[k] = wg[k];
        float brow = sm.bias[r];
        for (int v = 0; v < V_; v++) {
            const float4* em = reinterpret_cast<const float4*>(sm.embS + v * E_ + 16 * half);
            float a = 0.f;
            #pragma unroll
            for (int k = 0; k < 4; k++) {
                float4 e = em[k];
                a += we[k].x*e.x + we[k].y*e.y + we[k].z*e.z + we[k].w*e.w;
            }
            a += __shfl_xor_sync(0xffffffffu, a, 1);
            if (half == 0) sm.gate_emb[v * G4 + r] = a + brow;
        }
    }

    // ---- persistent P4 weights: 48 K-elements per thread (24 ull) ----
    // K layout (144, padded): [0:64)=W_ih ctx cols, [64:128)=W_hh cols, [128:144)=0
    ull wq2[24];
    {
        #pragma unroll
        for (int k = 0; k < 12; k++) {
            int j = t3 * 48 + 4 * k;
            float4 v;
            if (j < 64)        v = *reinterpret_cast<const float4*>(Wih + r4 * 96 + 32 + j);
            else if (j < 128)  v = *reinterpret_cast<const float4*>(Whh + r4 * 64 + (j - 64));
            else               v = make_float4(0.f, 0.f, 0.f, 0.f);
            wq2[2*k]   = pack2(v.x, v.y);
            wq2[2*k+1] = pack2(v.z, v.w);
        }
    }
    __syncthreads();

    float* outp = out + (size_t)b * T_ * V_;

    for (int t = 0; t < T_; t++) {
        // ---- P1 (tid<512): e_s = exp(enc[s,:].h) ----
        if (tid < 512) {
            const ull* ep = reinterpret_cast<const ull*>(sm.enc + r * ES + half * 34);
            const ull* hp = reinterpret_cast<const ull*>(sm.hdup + half * 40);
            ull a0 = 0ull, a1 = 0ull;
            #pragma unroll
            for (int k = 0; k < 16; k += 2) {
                a0 = fma2(ep[k],     hp[k],     a0);
                a1 = fma2(ep[k + 1], hp[k + 1], a1);
            }
            float2 fa = unpack2(a0), fb = unpack2(a1);
            float sc = (fa.x + fa.y) + (fb.x + fb.y);
            sc += __shfl_xor_sync(0xffffffffu, sc, 1);
            float e = __expf(sc);
            if (half == 0) sm.scores[r] = e;
            float su = e;
            #pragma unroll
            for (int o = 16; o > 1; o >>= 1)
                su += __shfl_xor_sync(0xffffffffu, su, o);
            if (lane == 0) sm.redsum[wrp] = su;   // warp's 16 distinct scores
        }
        __syncthreads();  // bar1

        // ---- P3 (warps 0-15): context partials ----
        if (wrp < 16) {
            const int sbase = wrp * 16;
            const float*  ebase = sm.enc + sbase * ES + 2 * lane + ((lane >> 4) & 1) * 2;
            const float4* sp = reinterpret_cast<const float4*>(sm.scores + sbase);
            float ax = 0.f, ay = 0.f;
            #pragma unroll
            for (int c = 0; c < 4; c++) {
                float4 sv = sp[c];
                float2 e0 = *reinterpret_cast<const float2*>(ebase + (4*c + 0) * ES);
                float2 e1 = *reinterpret_cast<const float2*>(ebase + (4*c + 1) * ES);
                float2 e2 = *reinterpret_cast<const float2*>(ebase + (4*c + 2) * ES);
                float2 e3 = *reinterpret_cast<const float2*>(ebase + (4*c + 3) * ES);
                ax += sv.x * e0.x; ay += sv.x * e0.y;
                ax += sv.y * e1.x; ay += sv.y * e1.y;
                ax += sv.z * e2.x; ay += sv.z * e2.y;
                ax += sv.w * e3.x; ay += sv.w * e3.y;
            }
            *reinterpret_cast<float2*>(&sm.part[wrp * 64 + 2 * lane]) = make_float2(ax, ay);
        }
        __syncthreads();  // bar2

        // ---- ctx reduce + normalize -> comb[64:), vec4 ctx chunks ----
        if (tid < H_) {
            float ssum = 0.f;
            #pragma unroll
            for (int k = 0; k < 16; k++) ssum += sm.redsum[k];
            float inv = 1.0f / ssum;
            float ctx = 0.f;
            #pragma unroll
            for (int q = 0; q < 16; q++) ctx += sm.part[q * 64 + tid];
            ctx *= inv;
            sm.comb[H_ + tid] = ctx;
            sm.vec4[tid + ((tid >= 48) ? 4 : 0)] = ctx;   // ctx at 0..47 / 52..67
        }
        __syncthreads();  // bar3

        // ---- P4: thread (r4, t3) does a 48-wide slice of the gate dot ----
        {
            const float4* vp = reinterpret_cast<const float4*>(sm.vec4 + t3 * 52);
            ull a0 = 0ull, a1 = 0ull;
            #pragma unroll
            for (int k = 0; k < 12; k++) {
                float4 xv = vp[k];
                a0 = fma2(wq2[2*k],   pack2(xv.x, xv.y), a0);
                a1 = fma2(wq2[2*k+1], pack2(xv.z, xv.w), a1);
            }
            float2 fa = unpack2(a0), fb = unpack2(a1);
            sm.gpart[t3 * G4 + r4] = (fa.x + fa.y) + (fb.x + fb.y);
        }
        __syncthreads();  // bar4

        // ---- P5: combine 3 partials + gate_emb, LSTM cell (i,f,g,o) ----
        if (tid < H_) {
            int tok = sm.ytok[t];
            const float* ge = sm.gate_emb + tok * G4;
            float g[4];
            #pragma unroll
            for (int gi = 0; gi < 4; gi++) {
                int row = gi * 64 + tid;
                g[gi] = sm.gpart[row] + sm.gpart[G4 + row] + sm.gpart[2*G4 + row]
                      + ge[row];
            }
            creg = sigmoid_(g[1]) * creg + sigmoid_(g[0]) * tanh_(g[2]);
            float hnew = sigmoid_(g[3]) * tanh_(creg);
            sm.comb[tid] = hnew;
            sm.hdup[tid + ((tid >> 5) << 3)] = hnew;
            sm.vec4[(tid < 32) ? (68 + tid) : (72 + tid)] = hnew;  // h chunks
        }
        __syncthreads();  // bar5

        // ---- P6 (tid<512): logits, 16 threads per vocab row ----
        if (tid < 512) {
            int v = tid >> 4, p = tid & 15;
            float acc = 0.0f;
            if (v < V_) {
                const float4* fw = reinterpret_cast<const float4*>(sm.fcW + v * 128 + p * 8);
                const float4* cb = reinterpret_cast<const float4*>(sm.comb + p * 8);
                float4 w0 = fw[0], w1 = fw[1];
                float4 c0v = cb[0], c1v = cb[1];
                acc = w0.x*c0v.x + w0.y*c0v.y + w0.z*c0v.z + w0.w*c0v.w
                    + w1.x*c1v.x + w1.y*c1v.y + w1.z*c1v.z + w1.w*c1v.w;
            }
            #pragma unroll
            for (int o = 8; o; o >>= 1)
                acc += __shfl_xor_sync(0xffffffffu, acc, o);
            if (p == 0 && v < V_)
                outp[t * V_ + v] = acc + sm.fcb[v];
        }
        // no trailing barrier: state P6 reads (comb, fcW) is next written only
        // after bar2/bar4 of step t+1; every warp must pass bar1(t+1) first,
        // which requires all warps to have finished their P6(t).
    }
}

extern "C" void kernel_launch(void* const* d_in, const int* in_sizes, int n_in,
                              void* d_out, int out_size) {
    const int*   y    = (const int*)d_in[0];
    const float* h0   = (const float*)d_in[1];
    const float* c0   = (const float*)d_in[2];
    const float* enc  = (const float*)d_in[3];
    const float* emb  = (const float*)d_in[4];
    const float* Wih  = (const float*)d_in[5];
    const float* Whh  = (const float*)d_in[6];
    const float* bih  = (const float*)d_in[7];
    const float* bhh  = (const float*)d_in[8];
    const float* fcW  = (const float*)d_in[9];
    const float* fcb  = (const float*)d_in[10];
    float* out = (float*)d_out;

    size_t smem = sizeof(Smem);
    cudaFuncSetAttribute(decoder_persist_kernel,
                         cudaFuncAttributeMaxDynamicSharedMemorySize, (int)smem);
    decoder_persist_kernel<<<B_, NT, smem>>>(y, h0, c0, enc, emb,
                                             Wih, Whh, bih, bhh, fcW, fcb, out);
}